// round 4
// baseline (speedup 1.0000x reference)
#include <cuda_runtime.h>
#include <cstdint>

#define N_NODES 25000
#define N_EDGES 400000
#define D       128
#define N_LAYERS 3
#define N_GRAPHS 512
#define D_OUT   10

typedef unsigned long long ull;

// ---------------- device scratch ----------------
__device__ float g_h[N_NODES * D];
__device__ float g_agg[N_NODES * D];
__device__ float g_z[N_NODES * D];
__device__ int   g_deg[N_NODES];
__device__ int   g_off[N_NODES + 1];
__device__ int   g_cur[N_NODES];
__device__ int   g_col[N_EDGES];

// ---------------- f32x2 packed helpers (sm_103a dual-rate FFMA) ----------
__device__ __forceinline__ void fma2(ull& d, ull a, ull b, ull c) {
    asm("fma.rn.f32x2 %0, %1, %2, %3;" : "=l"(d) : "l"(a), "l"(b), "l"(c));
}
__device__ __forceinline__ ull pack2(float x) {
    ull r; unsigned xi = __float_as_uint(x);
    asm("mov.b64 %0, {%1, %2};" : "=l"(r) : "r"(xi), "r"(xi));
    return r;
}
__device__ __forceinline__ float2 unpack2(ull v) {
    unsigned lo, hi;
    asm("mov.b64 {%0, %1}, %2;" : "=r"(lo), "=r"(hi) : "l"(v));
    return make_float2(__uint_as_float(lo), __uint_as_float(hi));
}

// ---------------- CSR build ----------------
__global__ void k_hist(const int* __restrict__ ei) {
    int e = blockIdx.x * blockDim.x + threadIdx.x;
    if (e < N_EDGES) atomicAdd(&g_deg[ei[N_EDGES + e]], 1);
}

// single-pass scan: 25 items/thread, one block reduction
__global__ void k_scan() {
    const int ITEMS = 25;   // 1024*25 = 25600 >= N_NODES
    __shared__ int wsum[32];
    int tid = threadIdx.x;
    int lane = tid & 31, warp = tid >> 5;
    int base = tid * ITEMS;
    int v[ITEMS];
    int s = 0;
    #pragma unroll
    for (int i = 0; i < ITEMS; i++) {
        int idx = base + i;
        v[i] = (idx < N_NODES) ? g_deg[idx] : 0;
        s += v[i];
    }
    int x = s;
    #pragma unroll
    for (int o = 1; o < 32; o <<= 1) {
        int y = __shfl_up_sync(0xFFFFFFFFu, x, o);
        if (lane >= o) x += y;
    }
    if (lane == 31) wsum[warp] = x;
    __syncthreads();
    if (tid < 32) {
        int w = wsum[tid];
        #pragma unroll
        for (int o = 1; o < 32; o <<= 1) {
            int y = __shfl_up_sync(0xFFFFFFFFu, w, o);
            if (tid >= o) w += y;
        }
        wsum[tid] = w;
    }
    __syncthreads();
    int excl = x - s + ((warp > 0) ? wsum[warp - 1] : 0);
    #pragma unroll
    for (int i = 0; i < ITEMS; i++) {
        int idx = base + i;
        if (idx < N_NODES) { g_off[idx] = excl; g_cur[idx] = excl; }
        excl += v[i];
    }
    if (tid == 1023) g_off[N_NODES] = excl;
}

__global__ void k_fill(const int* __restrict__ ei) {
    int e = blockIdx.x * blockDim.x + threadIdx.x;
    if (e < N_EDGES) {
        int s = ei[e];
        int d = ei[N_EDGES + e];
        int pos = atomicAdd(&g_cur[d], 1);
        g_col[pos] = s;
    }
}

// ---------------- GIN aggregation: one warp per node ----------------
__global__ void k_agg(const float* __restrict__ hin, const float* __restrict__ eps, int layer) {
    int gt = blockIdx.x * blockDim.x + threadIdx.x;
    int node = gt >> 5;
    if (node >= N_NODES) return;
    int lane = gt & 31;
    float epsv = 1.0f + eps[layer];
    const float4* h4 = (const float4*)hin;
    float4 self = h4[(size_t)node * 32 + lane];
    float4 acc;
    acc.x = self.x * epsv; acc.y = self.y * epsv;
    acc.z = self.z * epsv; acc.w = self.w * epsv;
    int e = g_off[node], end = g_off[node + 1];
    for (; e + 3 < end; e += 4) {
        int c0 = g_col[e], c1 = g_col[e + 1], c2 = g_col[e + 2], c3 = g_col[e + 3];
        float4 v0 = h4[(size_t)c0 * 32 + lane];
        float4 v1 = h4[(size_t)c1 * 32 + lane];
        float4 v2 = h4[(size_t)c2 * 32 + lane];
        float4 v3 = h4[(size_t)c3 * 32 + lane];
        acc.x += (v0.x + v1.x) + (v2.x + v3.x);
        acc.y += (v0.y + v1.y) + (v2.y + v3.y);
        acc.z += (v0.z + v1.z) + (v2.z + v3.z);
        acc.w += (v0.w + v1.w) + (v2.w + v3.w);
    }
    for (; e < end; e++) {
        int c = g_col[e];
        float4 v = h4[(size_t)c * 32 + lane];
        acc.x += v.x; acc.y += v.y; acc.z += v.z; acc.w += v.w;
    }
    ((float4*)g_agg)[(size_t)node * 32 + lane] = acc;
}

// ---------------- GEMM: [M,128] @ [128,128] in 64x64 tiles ----------------
// grid (ceil(M/64), 2); 128 threads; 4x8 microtile; f32x2 FMA; 3 CTAs/SM.
// MODE 0: out = relu(acc*s + t) (BN eval fused);  MODE 1: relu(acc + bias)
#define AS_STRIDE 132                    // pad 64x128 A tile: kill bank conflicts
#define GEMM_SMEM ((64 * AS_STRIDE + 128 * 64) * 4)   // 33792 + 32768 = 66560 B

template <int MODE>
__global__ void __launch_bounds__(128, 3) k_gemm(
    const float* __restrict__ A, const float* __restrict__ W, float* __restrict__ C,
    int M,
    const float* __restrict__ bias, const float* __restrict__ gamma,
    const float* __restrict__ beta, const float* __restrict__ mean,
    const float* __restrict__ var)
{
    extern __shared__ float smem[];
    float* As = smem;                    // 64 rows x stride 132
    float* Bs = smem + 64 * AS_STRIDE;   // 128 rows x 64 cols
    int tid = threadIdx.x;
    int m0 = blockIdx.x * 64;
    int n0 = blockIdx.y * 64;

    // load B half: Bs[k][c] = W[k][n0+c], k=0..127, c=0..63
    {
        const float* Wp = W + n0;
        #pragma unroll
        for (int i = 0; i < 16; i++) {
            int idx = tid + i * 128;          // 0..2047 float4s
            int k  = idx >> 4;
            int c4 = idx & 15;
            *(float4*)(Bs + k * 64 + c4 * 4) = *(const float4*)(Wp + (size_t)k * D + c4 * 4);
        }
    }
    // load A tile: As[r][c] = A[m0+r][c], padded stride
    {
        #pragma unroll
        for (int i = 0; i < 16; i++) {
            int idx = tid + i * 128;          // 0..2047 float4s
            int r  = idx >> 5;
            int c4 = idx & 31;
            int row = m0 + r;
            float4 v = (row < M) ? *(const float4*)(A + (size_t)row * D + c4 * 4)
                                 : make_float4(0.f, 0.f, 0.f, 0.f);
            *(float4*)(As + r * AS_STRIDE + c4 * 4) = v;
        }
    }
    __syncthreads();

    int tm = tid >> 3;   // 0..15 -> rows tm*4..tm*4+3
    int tn = tid & 7;    // 0..7  -> cols tn*8..tn*8+7
    ull acc[4][4];
    #pragma unroll
    for (int r = 0; r < 4; r++)
        #pragma unroll
        for (int j = 0; j < 4; j++) acc[r][j] = 0ull;

    const float* ap = As + tm * 4 * AS_STRIDE;
    #pragma unroll 4
    for (int k = 0; k < D; k++) {
        const ull* brow = (const ull*)(Bs + k * 64 + tn * 8);
        ull b0 = brow[0], b1 = brow[1], b2 = brow[2], b3 = brow[3];
        #pragma unroll
        for (int r = 0; r < 4; r++) {
            ull a2 = pack2(ap[r * AS_STRIDE + k]);
            fma2(acc[r][0], a2, b0, acc[r][0]);
            fma2(acc[r][1], a2, b1, acc[r][1]);
            fma2(acc[r][2], a2, b2, acc[r][2]);
            fma2(acc[r][3], a2, b3, acc[r][3]);
        }
    }

    #pragma unroll
    for (int j = 0; j < 4; j++) {
        int c0 = n0 + tn * 8 + 2 * j;
        float s0, t0, s1, t1;
        if (MODE == 0) {
            s0 = gamma[c0] * rsqrtf(var[c0] + 1e-5f);
            t0 = (bias[c0] - mean[c0]) * s0 + beta[c0];
            s1 = gamma[c0 + 1] * rsqrtf(var[c0 + 1] + 1e-5f);
            t1 = (bias[c0 + 1] - mean[c0 + 1]) * s1 + beta[c0 + 1];
        } else {
            s0 = 1.f; t0 = bias[c0];
            s1 = 1.f; t1 = bias[c0 + 1];
        }
        #pragma unroll
        for (int r = 0; r < 4; r++) {
            int row = m0 + tm * 4 + r;
            if (row < M) {
                float2 v = unpack2(acc[r][j]);
                float o0 = fmaxf(v.x * s0 + t0, 0.f);
                float o1 = fmaxf(v.y * s1 + t1, 0.f);
                *(float2*)(C + (size_t)row * D + c0) = make_float2(o0, o1);
            }
        }
    }
}

// ---------------- mean-pool per graph + final linear ----------------
__global__ void k_pool(const float* __restrict__ h, const int* __restrict__ batch,
                       const float* __restrict__ Wout, const float* __restrict__ bout,
                       float* __restrict__ out)
{
    int g = blockIdx.x;
    int t = threadIdx.x;   // 128

    int lo = 0, hi = N_NODES;
    while (lo < hi) { int mid = (lo + hi) >> 1; if (batch[mid] < g) lo = mid + 1; else hi = mid; }
    int start = lo;
    lo = start; hi = N_NODES;
    while (lo < hi) { int mid = (lo + hi) >> 1; if (batch[mid] < g + 1) lo = mid + 1; else hi = mid; }
    int stop = lo;

    float s = 0.f;
    for (int n = start; n < stop; n++) s += h[(size_t)n * D + t];
    float cnt = fmaxf((float)(stop - start), 1.f);

    __shared__ float sp[D];
    sp[t] = s / cnt;
    __syncthreads();

    if (t < D_OUT) {
        float acc = bout[t];
        #pragma unroll 8
        for (int k = 0; k < D; k++) acc += sp[k] * Wout[k * D_OUT + t];
        out[g * D_OUT + t] = acc;
    }
}

// ---------------- host launcher ----------------
extern "C" void kernel_launch(void* const* d_in, const int* in_sizes, int n_in,
                              void* d_out, int out_size)
{
    const float* x     = (const float*)d_in[0];
    const int*   ei    = (const int*)d_in[1];    // int32 (JAX x64 disabled)
    const int*   batch = (const int*)d_in[2];
    const float* W1    = (const float*)d_in[3];
    const float* b1    = (const float*)d_in[4];
    const float* gamma = (const float*)d_in[5];
    const float* beta  = (const float*)d_in[6];
    const float* rmean = (const float*)d_in[7];
    const float* rvar  = (const float*)d_in[8];
    const float* W2    = (const float*)d_in[9];
    const float* b2    = (const float*)d_in[10];
    const float* eps   = (const float*)d_in[11];
    const float* Wout  = (const float*)d_in[12];
    const float* bout  = (const float*)d_in[13];
    float* out = (float*)d_out;

    float *p_h, *p_agg, *p_z;
    int* p_deg;
    cudaGetSymbolAddress((void**)&p_h,   g_h);
    cudaGetSymbolAddress((void**)&p_agg, g_agg);
    cudaGetSymbolAddress((void**)&p_z,   g_z);
    cudaGetSymbolAddress((void**)&p_deg, g_deg);

    cudaFuncSetAttribute(k_gemm<0>, cudaFuncAttributeMaxDynamicSharedMemorySize, GEMM_SMEM);
    cudaFuncSetAttribute(k_gemm<1>, cudaFuncAttributeMaxDynamicSharedMemorySize, GEMM_SMEM);

    // ---- CSR build (recomputed every call: deterministic) ----
    cudaMemsetAsync(p_deg, 0, N_NODES * sizeof(int));
    k_hist<<<(N_EDGES + 255) / 256, 256>>>(ei);
    k_scan<<<1, 1024>>>();
    k_fill<<<(N_EDGES + 255) / 256, 256>>>(ei);

    const dim3 gemm_grid((N_NODES + 63) / 64, 2);   // 391 x 2
    const int agg_blocks = (N_NODES * 32 + 255) / 256;

    for (int l = 0; l < N_LAYERS; l++) {
        const float* hin = (l == 0) ? x : p_h;
        k_agg<<<agg_blocks, 256>>>(hin, eps, l);
        k_gemm<0><<<gemm_grid, 128, GEMM_SMEM>>>(
            p_agg, W1 + (size_t)l * D * D, p_z, N_NODES,
            b1 + l * D, gamma + l * D, beta + l * D, rmean + l * D, rvar + l * D);
        k_gemm<1><<<gemm_grid, 128, GEMM_SMEM>>>(
            p_z, W2 + (size_t)l * D * D, p_h, N_NODES,
            b2 + l * D, (const float*)0, (const float*)0, (const float*)0, (const float*)0);
    }

    k_pool<<<N_GRAPHS, D>>>(p_h, batch, Wout, bout, out);
}

// round 5
// speedup vs baseline: 1.0063x; 1.0063x over previous
#include <cuda_runtime.h>
#include <cstdint>

#define N_NODES 25000
#define N_EDGES 400000
#define D       128
#define N_LAYERS 3
#define N_GRAPHS 512
#define D_OUT   10

typedef unsigned long long ull;

// ---------------- device scratch ----------------
__device__ float g_h[N_NODES * D];
__device__ float g_agg[N_NODES * D];
__device__ float g_z[N_NODES * D];
__device__ int   g_deg[N_NODES];
__device__ int   g_off[N_NODES + 1];
__device__ int   g_cur[N_NODES];
__device__ int   g_col[N_EDGES];

// ---------------- f32x2 packed helpers (sm_103a dual-rate FFMA) ----------
__device__ __forceinline__ void fma2(ull& d, ull a, ull b, ull c) {
    asm("fma.rn.f32x2 %0, %1, %2, %3;" : "=l"(d) : "l"(a), "l"(b), "l"(c));
}
__device__ __forceinline__ ull pack2(float x) {
    ull r; unsigned xi = __float_as_uint(x);
    asm("mov.b64 %0, {%1, %2};" : "=l"(r) : "r"(xi), "r"(xi));
    return r;
}
__device__ __forceinline__ float2 unpack2(ull v) {
    unsigned lo, hi;
    asm("mov.b64 {%0, %1}, %2;" : "=r"(lo), "=r"(hi) : "l"(v));
    return make_float2(__uint_as_float(lo), __uint_as_float(hi));
}

// ---------------- CSR build ----------------
__global__ void k_hist(const int* __restrict__ ei) {
    int e = blockIdx.x * blockDim.x + threadIdx.x;
    if (e < N_EDGES) atomicAdd(&g_deg[ei[N_EDGES + e]], 1);
}

// single-pass scan: 25 items/thread, one block reduction
__global__ void k_scan() {
    const int ITEMS = 25;   // 1024*25 = 25600 >= N_NODES
    __shared__ int wsum[32];
    int tid = threadIdx.x;
    int lane = tid & 31, warp = tid >> 5;
    int base = tid * ITEMS;
    int v[ITEMS];
    int s = 0;
    #pragma unroll
    for (int i = 0; i < ITEMS; i++) {
        int idx = base + i;
        v[i] = (idx < N_NODES) ? g_deg[idx] : 0;
        s += v[i];
    }
    int x = s;
    #pragma unroll
    for (int o = 1; o < 32; o <<= 1) {
        int y = __shfl_up_sync(0xFFFFFFFFu, x, o);
        if (lane >= o) x += y;
    }
    if (lane == 31) wsum[warp] = x;
    __syncthreads();
    if (tid < 32) {
        int w = wsum[tid];
        #pragma unroll
        for (int o = 1; o < 32; o <<= 1) {
            int y = __shfl_up_sync(0xFFFFFFFFu, w, o);
            if (tid >= o) w += y;
        }
        wsum[tid] = w;
    }
    __syncthreads();
    int excl = x - s + ((warp > 0) ? wsum[warp - 1] : 0);
    #pragma unroll
    for (int i = 0; i < ITEMS; i++) {
        int idx = base + i;
        if (idx < N_NODES) { g_off[idx] = excl; g_cur[idx] = excl; }
        excl += v[i];
    }
    if (tid == 1023) g_off[N_NODES] = excl;
}

__global__ void k_fill(const int* __restrict__ ei) {
    int e = blockIdx.x * blockDim.x + threadIdx.x;
    if (e < N_EDGES) {
        int s = ei[e];
        int d = ei[N_EDGES + e];
        int pos = atomicAdd(&g_cur[d], 1);
        g_col[pos] = s;
    }
}

// ---------------- GIN aggregation: one warp per node ----------------
__global__ void k_agg(const float* __restrict__ hin, const float* __restrict__ eps, int layer) {
    int gt = blockIdx.x * blockDim.x + threadIdx.x;
    int node = gt >> 5;
    if (node >= N_NODES) return;
    int lane = gt & 31;
    float epsv = 1.0f + eps[layer];
    const float4* h4 = (const float4*)hin;
    float4 self = h4[(size_t)node * 32 + lane];
    float4 acc;
    acc.x = self.x * epsv; acc.y = self.y * epsv;
    acc.z = self.z * epsv; acc.w = self.w * epsv;
    int e = g_off[node], end = g_off[node + 1];
    for (; e + 3 < end; e += 4) {
        int c0 = g_col[e], c1 = g_col[e + 1], c2 = g_col[e + 2], c3 = g_col[e + 3];
        float4 v0 = h4[(size_t)c0 * 32 + lane];
        float4 v1 = h4[(size_t)c1 * 32 + lane];
        float4 v2 = h4[(size_t)c2 * 32 + lane];
        float4 v3 = h4[(size_t)c3 * 32 + lane];
        acc.x += (v0.x + v1.x) + (v2.x + v3.x);
        acc.y += (v0.y + v1.y) + (v2.y + v3.y);
        acc.z += (v0.z + v1.z) + (v2.z + v3.z);
        acc.w += (v0.w + v1.w) + (v2.w + v3.w);
    }
    for (; e < end; e++) {
        int c = g_col[e];
        float4 v = h4[(size_t)c * 32 + lane];
        acc.x += v.x; acc.y += v.y; acc.z += v.z; acc.w += v.w;
    }
    ((float4*)g_agg)[(size_t)node * 32 + lane] = acc;
}

// ---------------- GEMM: [M,128]@[128,128], 96x128 tile, single wave ----------
// 384 threads (24x16), 4x8 microtile, f32x2 FMA.
// Grid = ceil(M/96) = 261 CTAs @ 2 CTA/SM -> ONE wave on 148 SMs.
// smem: A 96x128 (48KB, unpadded: warps see only 2 A-rows -> broadcast) +
//       B 128x128 (64KB) = 112KB; 2 blocks = 224KB <= 228KB/SM.
// MODE 0: out = relu(acc*s + t) (BN eval fused);  MODE 1: relu(acc + bias)
#define TILE_M 96
#define GEMM_SMEM ((TILE_M * D + D * D) * 4)   // 49152 + 65536 = 114688 B

template <int MODE>
__global__ void __launch_bounds__(384, 2) k_gemm(
    const float* __restrict__ A, const float* __restrict__ W, float* __restrict__ C,
    int M,
    const float* __restrict__ bias, const float* __restrict__ gamma,
    const float* __restrict__ beta, const float* __restrict__ mean,
    const float* __restrict__ var)
{
    extern __shared__ float smem[];
    float* As = smem;                 // 96 x 128
    float* Bs = smem + TILE_M * D;    // 128 x 128
    int tid = threadIdx.x;
    int m0 = blockIdx.x * TILE_M;

    // load B (128x128 = 4096 float4)
    {
        const float4* W4 = (const float4*)W;
        float4* Bs4 = (float4*)Bs;
        #pragma unroll
        for (int i = 0; i < 11; i++) {
            int idx = tid + i * 384;
            if (idx < 4096) Bs4[idx] = W4[idx];
        }
    }
    // load A tile (96x32 float4 = 3072)
    {
        const float4* A4 = (const float4*)A;
        float4* As4 = (float4*)As;
        #pragma unroll
        for (int i = 0; i < 8; i++) {
            int idx = tid + i * 384;          // 0..3071
            int r  = idx >> 5;
            int c4 = idx & 31;
            int row = m0 + r;
            As4[idx] = (row < M) ? A4[(size_t)row * 32 + c4]
                                 : make_float4(0.f, 0.f, 0.f, 0.f);
        }
    }
    __syncthreads();

    int tm = tid >> 4;   // 0..23 -> rows tm*4..tm*4+3
    int tn = tid & 15;   // 0..15 -> cols tn*8..tn*8+7
    ull acc[4][4];
    #pragma unroll
    for (int r = 0; r < 4; r++)
        #pragma unroll
        for (int j = 0; j < 4; j++) acc[r][j] = 0ull;

    const float* ap = As + tm * 4 * D;
    #pragma unroll 8
    for (int k = 0; k < D; k++) {
        const ull* brow = (const ull*)(Bs + k * D + tn * 8);
        ull b0 = brow[0], b1 = brow[1], b2 = brow[2], b3 = brow[3];
        #pragma unroll
        for (int r = 0; r < 4; r++) {
            ull a2 = pack2(ap[r * D + k]);
            fma2(acc[r][0], a2, b0, acc[r][0]);
            fma2(acc[r][1], a2, b1, acc[r][1]);
            fma2(acc[r][2], a2, b2, acc[r][2]);
            fma2(acc[r][3], a2, b3, acc[r][3]);
        }
    }

    #pragma unroll
    for (int j = 0; j < 4; j++) {
        int c0 = tn * 8 + 2 * j;
        float s0, t0, s1, t1;
        if (MODE == 0) {
            s0 = gamma[c0] * rsqrtf(var[c0] + 1e-5f);
            t0 = (bias[c0] - mean[c0]) * s0 + beta[c0];
            s1 = gamma[c0 + 1] * rsqrtf(var[c0 + 1] + 1e-5f);
            t1 = (bias[c0 + 1] - mean[c0 + 1]) * s1 + beta[c0 + 1];
        } else {
            s0 = 1.f; t0 = bias[c0];
            s1 = 1.f; t1 = bias[c0 + 1];
        }
        #pragma unroll
        for (int r = 0; r < 4; r++) {
            int row = m0 + tm * 4 + r;
            if (row < M) {
                float2 v = unpack2(acc[r][j]);
                float o0 = fmaxf(v.x * s0 + t0, 0.f);
                float o1 = fmaxf(v.y * s1 + t1, 0.f);
                *(float2*)(C + (size_t)row * D + c0) = make_float2(o0, o1);
            }
        }
    }
}

// ---------------- mean-pool per graph + final linear ----------------
__global__ void k_pool(const float* __restrict__ h, const int* __restrict__ batch,
                       const float* __restrict__ Wout, const float* __restrict__ bout,
                       float* __restrict__ out)
{
    int g = blockIdx.x;
    int t = threadIdx.x;   // 128

    int lo = 0, hi = N_NODES;
    while (lo < hi) { int mid = (lo + hi) >> 1; if (batch[mid] < g) lo = mid + 1; else hi = mid; }
    int start = lo;
    lo = start; hi = N_NODES;
    while (lo < hi) { int mid = (lo + hi) >> 1; if (batch[mid] < g + 1) lo = mid + 1; else hi = mid; }
    int stop = lo;

    float s = 0.f;
    for (int n = start; n < stop; n++) s += h[(size_t)n * D + t];
    float cnt = fmaxf((float)(stop - start), 1.f);

    __shared__ float sp[D];
    sp[t] = s / cnt;
    __syncthreads();

    if (t < D_OUT) {
        float acc = bout[t];
        #pragma unroll 8
        for (int k = 0; k < D; k++) acc += sp[k] * Wout[k * D_OUT + t];
        out[g * D_OUT + t] = acc;
    }
}

// ---------------- host launcher ----------------
extern "C" void kernel_launch(void* const* d_in, const int* in_sizes, int n_in,
                              void* d_out, int out_size)
{
    const float* x     = (const float*)d_in[0];
    const int*   ei    = (const int*)d_in[1];    // int32 (JAX x64 disabled)
    const int*   batch = (const int*)d_in[2];
    const float* W1    = (const float*)d_in[3];
    const float* b1    = (const float*)d_in[4];
    const float* gamma = (const float*)d_in[5];
    const float* beta  = (const float*)d_in[6];
    const float* rmean = (const float*)d_in[7];
    const float* rvar  = (const float*)d_in[8];
    const float* W2    = (const float*)d_in[9];
    const float* b2    = (const float*)d_in[10];
    const float* eps   = (const float*)d_in[11];
    const float* Wout  = (const float*)d_in[12];
    const float* bout  = (const float*)d_in[13];
    float* out = (float*)d_out;

    float *p_h, *p_agg, *p_z;
    int* p_deg;
    cudaGetSymbolAddress((void**)&p_h,   g_h);
    cudaGetSymbolAddress((void**)&p_agg, g_agg);
    cudaGetSymbolAddress((void**)&p_z,   g_z);
    cudaGetSymbolAddress((void**)&p_deg, g_deg);

    cudaFuncSetAttribute(k_gemm<0>, cudaFuncAttributeMaxDynamicSharedMemorySize, GEMM_SMEM);
    cudaFuncSetAttribute(k_gemm<1>, cudaFuncAttributeMaxDynamicSharedMemorySize, GEMM_SMEM);

    // ---- CSR build (recomputed every call: deterministic) ----
    cudaMemsetAsync(p_deg, 0, N_NODES * sizeof(int));
    k_hist<<<(N_EDGES + 255) / 256, 256>>>(ei);
    k_scan<<<1, 1024>>>();
    k_fill<<<(N_EDGES + 255) / 256, 256>>>(ei);

    const int gemm_blocks = (N_NODES + TILE_M - 1) / TILE_M;   // 261
    const int agg_blocks  = (N_NODES * 32 + 255) / 256;

    for (int l = 0; l < N_LAYERS; l++) {
        const float* hin = (l == 0) ? x : p_h;
        k_agg<<<agg_blocks, 256>>>(hin, eps, l);
        k_gemm<0><<<gemm_blocks, 384, GEMM_SMEM>>>(
            p_agg, W1 + (size_t)l * D * D, p_z, N_NODES,
            b1 + l * D, gamma + l * D, beta + l * D, rmean + l * D, rvar + l * D);
        k_gemm<1><<<gemm_blocks, 384, GEMM_SMEM>>>(
            p_z, W2 + (size_t)l * D * D, p_h, N_NODES,
            b2 + l * D, (const float*)0, (const float*)0, (const float*)0, (const float*)0);
    }

    k_pool<<<N_GRAPHS, D>>>(p_h, batch, Wout, bout, out);
}

// round 6
// speedup vs baseline: 1.1951x; 1.1876x over previous
#include <cuda_runtime.h>
#include <cstdint>

#define N_NODES 25000
#define N_EDGES 400000
#define D       128
#define N_LAYERS 3
#define N_GRAPHS 512
#define D_OUT   10

typedef unsigned long long ull;

// ---------------- device scratch ----------------
__device__ float g_h[N_NODES * D];
__device__ float g_agg[N_NODES * D];
__device__ float g_z[N_NODES * D];
__device__ int   g_deg[N_NODES];
__device__ int   g_off[N_NODES + 1];
__device__ int   g_cur[N_NODES];
__device__ int   g_col[N_EDGES];

// ---------------- f32x2 packed helpers ----------
__device__ __forceinline__ void fma2(ull& d, ull a, ull b, ull c) {
    asm("fma.rn.f32x2 %0, %1, %2, %3;" : "=l"(d) : "l"(a), "l"(b), "l"(c));
}
__device__ __forceinline__ ull pack2(float x) {
    ull r; unsigned xi = __float_as_uint(x);
    asm("mov.b64 %0, {%1, %2};" : "=l"(r) : "r"(xi), "r"(xi));
    return r;
}
__device__ __forceinline__ float2 unpack2(ull v) {
    unsigned lo, hi;
    asm("mov.b64 {%0, %1}, %2;" : "=r"(lo), "=r"(hi) : "l"(v));
    return make_float2(__uint_as_float(lo), __uint_as_float(hi));
}

// ---------------- CSR build ----------------
__global__ void k_hist(const int* __restrict__ ei) {
    int e = blockIdx.x * blockDim.x + threadIdx.x;
    if (e < N_EDGES) atomicAdd(&g_deg[ei[N_EDGES + e]], 1);
}

__global__ void k_scan() {
    const int ITEMS = 25;
    __shared__ int wsum[32];
    int tid = threadIdx.x;
    int lane = tid & 31, warp = tid >> 5;
    int base = tid * ITEMS;
    int v[ITEMS];
    int s = 0;
    #pragma unroll
    for (int i = 0; i < ITEMS; i++) {
        int idx = base + i;
        v[i] = (idx < N_NODES) ? g_deg[idx] : 0;
        s += v[i];
    }
    int x = s;
    #pragma unroll
    for (int o = 1; o < 32; o <<= 1) {
        int y = __shfl_up_sync(0xFFFFFFFFu, x, o);
        if (lane >= o) x += y;
    }
    if (lane == 31) wsum[warp] = x;
    __syncthreads();
    if (tid < 32) {
        int w = wsum[tid];
        #pragma unroll
        for (int o = 1; o < 32; o <<= 1) {
            int y = __shfl_up_sync(0xFFFFFFFFu, w, o);
            if (tid >= o) w += y;
        }
        wsum[tid] = w;
    }
    __syncthreads();
    int excl = x - s + ((warp > 0) ? wsum[warp - 1] : 0);
    #pragma unroll
    for (int i = 0; i < ITEMS; i++) {
        int idx = base + i;
        if (idx < N_NODES) { g_off[idx] = excl; g_cur[idx] = excl; }
        excl += v[i];
    }
    if (tid == 1023) g_off[N_NODES] = excl;
}

__global__ void k_fill(const int* __restrict__ ei) {
    int e = blockIdx.x * blockDim.x + threadIdx.x;
    if (e < N_EDGES) {
        int s = ei[e];
        int d = ei[N_EDGES + e];
        int pos = atomicAdd(&g_cur[d], 1);
        g_col[pos] = s;
    }
}

// ---------------- GIN aggregation: one warp per node ----------------
__global__ void k_agg(const float* __restrict__ hin, const float* __restrict__ eps, int layer) {
    int gt = blockIdx.x * blockDim.x + threadIdx.x;
    int node = gt >> 5;
    if (node >= N_NODES) return;
    int lane = gt & 31;
    float epsv = 1.0f + eps[layer];
    const float4* h4 = (const float4*)hin;
    float4 self = h4[(size_t)node * 32 + lane];
    float4 acc;
    acc.x = self.x * epsv; acc.y = self.y * epsv;
    acc.z = self.z * epsv; acc.w = self.w * epsv;
    int e = g_off[node], end = g_off[node + 1];
    for (; e + 3 < end; e += 4) {
        int c0 = g_col[e], c1 = g_col[e + 1], c2 = g_col[e + 2], c3 = g_col[e + 3];
        float4 v0 = h4[(size_t)c0 * 32 + lane];
        float4 v1 = h4[(size_t)c1 * 32 + lane];
        float4 v2 = h4[(size_t)c2 * 32 + lane];
        float4 v3 = h4[(size_t)c3 * 32 + lane];
        acc.x += (v0.x + v1.x) + (v2.x + v3.x);
        acc.y += (v0.y + v1.y) + (v2.y + v3.y);
        acc.z += (v0.z + v1.z) + (v2.z + v3.z);
        acc.w += (v0.w + v1.w) + (v2.w + v3.w);
    }
    for (; e < end; e++) {
        int c = g_col[e];
        float4 v = h4[(size_t)c * 32 + lane];
        acc.x += v.x; acc.y += v.y; acc.z += v.z; acc.w += v.w;
    }
    ((float4*)g_agg)[(size_t)node * 32 + lane] = acc;
}

// ---------------- GEMM: [M,128]@[128,128], 96x128 tile -----------------
// 256 threads = 8 warps. Warp w owns columns [w*16, w*16+16).
// Lane l accumulates rows l, l+32, l+64 (3x16 microtile, 24 FFMA2/k).
// B loads: all lanes of a warp read the SAME 16 floats -> broadcast, free.
// A loads: stride-129 padding -> bank (lane+k)%32 -> conflict-free.
// smem 115072B -> 2 CTA/SM; grid 261 CTAs ~ one wave.
// MODE 0: relu(acc*s + t) (BN eval fused);  MODE 1: relu(acc + bias)
#define TILE_M    96
#define AS_STRIDE 129
#define GEMM_SMEM ((TILE_M * AS_STRIDE + D * D) * 4)   // 49536 + 65536 = 115072

template <int MODE>
__global__ void __launch_bounds__(256, 2) k_gemm(
    const float* __restrict__ A, const float* __restrict__ W, float* __restrict__ C,
    int M,
    const float* __restrict__ bias, const float* __restrict__ gamma,
    const float* __restrict__ beta, const float* __restrict__ mean,
    const float* __restrict__ var)
{
    extern __shared__ float smem[];
    float* As = smem;                          // 96 x 129 (padded)
    float* Bs = smem + TILE_M * AS_STRIDE;     // 128 x 128
    int tid = threadIdx.x;
    int m0 = blockIdx.x * TILE_M;

    // load B (4096 float4, direct copy)
    {
        const float4* W4 = (const float4*)W;
        float4* Bs4 = (float4*)Bs;
        #pragma unroll
        for (int i = 0; i < 16; i++) Bs4[tid + i * 256] = W4[tid + i * 256];
    }
    // load A tile -> stride-129 smem (scalar stores; padded rows)
    {
        #pragma unroll
        for (int i = 0; i < 12; i++) {
            int idx = tid + i * 256;            // 0..3071 float4-chunks
            int r  = idx >> 5;
            int c0 = (idx & 31) * 4;
            int row = m0 + r;
            float4 v = (row < M) ? *(const float4*)(A + (size_t)row * D + c0)
                                 : make_float4(0.f, 0.f, 0.f, 0.f);
            float* dst = As + r * AS_STRIDE + c0;
            dst[0] = v.x; dst[1] = v.y; dst[2] = v.z; dst[3] = v.w;
        }
    }
    __syncthreads();

    int warp = tid >> 5;
    int lane = tid & 31;
    int n0 = warp * 16;

    ull acc[3][8];
    #pragma unroll
    for (int j = 0; j < 3; j++)
        #pragma unroll
        for (int p = 0; p < 8; p++) acc[j][p] = 0ull;

    const float* a0 = As + lane * AS_STRIDE;
    const float* a1 = As + (lane + 32) * AS_STRIDE;
    const float* a2p = As + (lane + 64) * AS_STRIDE;
    const float* bp = Bs + n0;

    #pragma unroll 4
    for (int k = 0; k < D; k++) {
        const ull* br = (const ull*)(bp + (size_t)k * D);   // 16 floats, broadcast
        ull b0 = br[0], b1 = br[1], b2 = br[2], b3 = br[3];
        ull b4 = br[4], b5 = br[5], b6 = br[6], b7 = br[7];
        ull x0 = pack2(a0[k]);
        ull x1 = pack2(a1[k]);
        ull x2 = pack2(a2p[k]);
        fma2(acc[0][0], x0, b0, acc[0][0]); fma2(acc[0][1], x0, b1, acc[0][1]);
        fma2(acc[0][2], x0, b2, acc[0][2]); fma2(acc[0][3], x0, b3, acc[0][3]);
        fma2(acc[0][4], x0, b4, acc[0][4]); fma2(acc[0][5], x0, b5, acc[0][5]);
        fma2(acc[0][6], x0, b6, acc[0][6]); fma2(acc[0][7], x0, b7, acc[0][7]);
        fma2(acc[1][0], x1, b0, acc[1][0]); fma2(acc[1][1], x1, b1, acc[1][1]);
        fma2(acc[1][2], x1, b2, acc[1][2]); fma2(acc[1][3], x1, b3, acc[1][3]);
        fma2(acc[1][4], x1, b4, acc[1][4]); fma2(acc[1][5], x1, b5, acc[1][5]);
        fma2(acc[1][6], x1, b6, acc[1][6]); fma2(acc[1][7], x1, b7, acc[1][7]);
        fma2(acc[2][0], x2, b0, acc[2][0]); fma2(acc[2][1], x2, b1, acc[2][1]);
        fma2(acc[2][2], x2, b2, acc[2][2]); fma2(acc[2][3], x2, b3, acc[2][3]);
        fma2(acc[2][4], x2, b4, acc[2][4]); fma2(acc[2][5], x2, b5, acc[2][5]);
        fma2(acc[2][6], x2, b6, acc[2][6]); fma2(acc[2][7], x2, b7, acc[2][7]);
    }

    // epilogue constants into As (free scratch now): s[128] at As[0..], t at As[128..]
    __syncthreads();
    if (tid < 128) {
        float s, t;
        if (MODE == 0) {
            s = gamma[tid] * rsqrtf(var[tid] + 1e-5f);
            t = (bias[tid] - mean[tid]) * s + beta[tid];
        } else {
            s = 1.0f; t = bias[tid];
        }
        As[tid] = s;
        As[128 + tid] = t;
    }
    __syncthreads();

    float sc[16], sh[16];
    #pragma unroll
    for (int c = 0; c < 16; c++) { sc[c] = As[n0 + c]; sh[c] = As[128 + n0 + c]; }

    #pragma unroll
    for (int j = 0; j < 3; j++) {
        int row = m0 + lane + 32 * j;
        if (row < M) {
            float* cp = C + (size_t)row * D + n0;
            #pragma unroll
            for (int p = 0; p < 8; p++) {
                float2 v = unpack2(acc[j][p]);
                float o0 = fmaxf(fmaf(v.x, sc[2*p],     sh[2*p]),     0.f);
                float o1 = fmaxf(fmaf(v.y, sc[2*p + 1], sh[2*p + 1]), 0.f);
                *(float2*)(cp + 2 * p) = make_float2(o0, o1);
            }
        }
    }
}

// ---------------- mean-pool per graph + final linear ----------------
__global__ void k_pool(const float* __restrict__ h, const int* __restrict__ batch,
                       const float* __restrict__ Wout, const float* __restrict__ bout,
                       float* __restrict__ out)
{
    int g = blockIdx.x;
    int t = threadIdx.x;   // 128

    int lo = 0, hi = N_NODES;
    while (lo < hi) { int mid = (lo + hi) >> 1; if (batch[mid] < g) lo = mid + 1; else hi = mid; }
    int start = lo;
    lo = start; hi = N_NODES;
    while (lo < hi) { int mid = (lo + hi) >> 1; if (batch[mid] < g + 1) lo = mid + 1; else hi = mid; }
    int stop = lo;

    float s = 0.f;
    for (int n = start; n < stop; n++) s += h[(size_t)n * D + t];
    float cnt = fmaxf((float)(stop - start), 1.f);

    __shared__ float sp[D];
    sp[t] = s / cnt;
    __syncthreads();

    if (t < D_OUT) {
        float acc = bout[t];
        #pragma unroll 8
        for (int k = 0; k < D; k++) acc += sp[k] * Wout[k * D_OUT + t];
        out[g * D_OUT + t] = acc;
    }
}

// ---------------- host launcher ----------------
extern "C" void kernel_launch(void* const* d_in, const int* in_sizes, int n_in,
                              void* d_out, int out_size)
{
    const float* x     = (const float*)d_in[0];
    const int*   ei    = (const int*)d_in[1];    // int32 (JAX x64 disabled)
    const int*   batch = (const int*)d_in[2];
    const float* W1    = (const float*)d_in[3];
    const float* b1    = (const float*)d_in[4];
    const float* gamma = (const float*)d_in[5];
    const float* beta  = (const float*)d_in[6];
    const float* rmean = (const float*)d_in[7];
    const float* rvar  = (const float*)d_in[8];
    const float* W2    = (const float*)d_in[9];
    const float* b2    = (const float*)d_in[10];
    const float* eps   = (const float*)d_in[11];
    const float* Wout  = (const float*)d_in[12];
    const float* bout  = (const float*)d_in[13];
    float* out = (float*)d_out;

    float *p_h, *p_agg, *p_z;
    int* p_deg;
    cudaGetSymbolAddress((void**)&p_h,   g_h);
    cudaGetSymbolAddress((void**)&p_agg, g_agg);
    cudaGetSymbolAddress((void**)&p_z,   g_z);
    cudaGetSymbolAddress((void**)&p_deg, g_deg);

    cudaFuncSetAttribute(k_gemm<0>, cudaFuncAttributeMaxDynamicSharedMemorySize, GEMM_SMEM);
    cudaFuncSetAttribute(k_gemm<1>, cudaFuncAttributeMaxDynamicSharedMemorySize, GEMM_SMEM);

    // ---- CSR build (recomputed every call: deterministic) ----
    cudaMemsetAsync(p_deg, 0, N_NODES * sizeof(int));
    k_hist<<<(N_EDGES + 255) / 256, 256>>>(ei);
    k_scan<<<1, 1024>>>();
    k_fill<<<(N_EDGES + 255) / 256, 256>>>(ei);

    const int gemm_blocks = (N_NODES + TILE_M - 1) / TILE_M;   // 261
    const int agg_blocks  = (N_NODES * 32 + 255) / 256;

    for (int l = 0; l < N_LAYERS; l++) {
        const float* hin = (l == 0) ? x : p_h;
        k_agg<<<agg_blocks, 256>>>(hin, eps, l);
        k_gemm<0><<<gemm_blocks, 256, GEMM_SMEM>>>(
            p_agg, W1 + (size_t)l * D * D, p_z, N_NODES,
            b1 + l * D, gamma + l * D, beta + l * D, rmean + l * D, rvar + l * D);
        k_gemm<1><<<gemm_blocks, 256, GEMM_SMEM>>>(
            p_z, W2 + (size_t)l * D * D, p_h, N_NODES,
            b2 + l * D, (const float*)0, (const float*)0, (const float*)0, (const float*)0);
    }

    k_pool<<<N_GRAPHS, D>>>(p_h, batch, Wout, bout, out);
}